// round 1
// baseline (speedup 1.0000x reference)
#include <cuda_runtime.h>
#include <stdint.h>

// ---------------------------------------------------------------------------
// JAX threefry2x32 reproduction.
// JAX >= 0.4.36 defaults jax_threefry_partitionable=True:
//   split(key, 8):  ks[i] = threefry(key, (0, i))          (both lanes)
//   random_bits32(key, shape) elem i: lane0 ^ lane1 of threefry(key, (0, i))
// Legacy (partitionable=False) scheme kept behind the macro as fallback.
// ---------------------------------------------------------------------------
#define JAX_PARTITIONABLE 1

#define TB 128
#define XSTRIDE 68

struct Keys { unsigned int k[16]; };   // ks[i] = (k[2i], k[2i+1])

__device__ float g_nw[3328];           // noisy weights, k-major per layer
                                       // offsets: L1:0 (64x32) L2:2048 (32x24)
                                       //          L3:2816 (24x16) L4:3200 (16x8)

__host__ __device__ __forceinline__ void tf2x32(uint32_t k0, uint32_t k1,
                                                uint32_t x0, uint32_t x1,
                                                uint32_t* o0, uint32_t* o1) {
  uint32_t ks2 = k0 ^ k1 ^ 0x1BD11BDAu;
#define TFR(a,b,r) { a += b; b = ((b << (r)) | (b >> (32 - (r)))); b ^= a; }
  x0 += k0; x1 += k1;
  TFR(x0,x1,13) TFR(x0,x1,15) TFR(x0,x1,26) TFR(x0,x1,6)
  x0 += k1;  x1 += ks2 + 1u;
  TFR(x0,x1,17) TFR(x0,x1,29) TFR(x0,x1,16) TFR(x0,x1,24)
  x0 += ks2; x1 += k0 + 2u;
  TFR(x0,x1,13) TFR(x0,x1,15) TFR(x0,x1,26) TFR(x0,x1,6)
  x0 += k0;  x1 += k1 + 3u;
  TFR(x0,x1,17) TFR(x0,x1,29) TFR(x0,x1,16) TFR(x0,x1,24)
  x0 += k1;  x1 += ks2 + 4u;
  TFR(x0,x1,13) TFR(x0,x1,15) TFR(x0,x1,26) TFR(x0,x1,6)
  x0 += ks2; x1 += k0 + 5u;
#undef TFR
  *o0 = x0; *o1 = x1;
}

// XLA ErfInv f32 expansion (Giles polynomial), mul/add separated (no FMA
// contraction) to match XLA's elementwise lowering.
__device__ __forceinline__ float erfinv_xla(float x) {
  float xx = __fmul_rn(x, x);
  float w  = -log1pf(-xx);
  float p;
  if (w < 5.0f) {
    w = __fadd_rn(w, -2.5f);
    p = 2.81022636e-08f;
    p = __fadd_rn(3.43273939e-07f,  __fmul_rn(p, w));
    p = __fadd_rn(-3.5233877e-06f,  __fmul_rn(p, w));
    p = __fadd_rn(-4.39150654e-06f, __fmul_rn(p, w));
    p = __fadd_rn(0.00021858087f,   __fmul_rn(p, w));
    p = __fadd_rn(-0.00125372503f,  __fmul_rn(p, w));
    p = __fadd_rn(-0.00417768164f,  __fmul_rn(p, w));
    p = __fadd_rn(0.246640727f,     __fmul_rn(p, w));
    p = __fadd_rn(1.50140941f,      __fmul_rn(p, w));
  } else {
    w = __fadd_rn(sqrtf(w), -3.0f);
    p = -0.000200214257f;
    p = __fadd_rn(0.000100950558f,  __fmul_rn(p, w));
    p = __fadd_rn(0.00134934322f,   __fmul_rn(p, w));
    p = __fadd_rn(-0.00367342844f,  __fmul_rn(p, w));
    p = __fadd_rn(0.00573950773f,   __fmul_rn(p, w));
    p = __fadd_rn(-0.0076224613f,   __fmul_rn(p, w));
    p = __fadd_rn(0.00943887047f,   __fmul_rn(p, w));
    p = __fadd_rn(1.00167406f,      __fmul_rn(p, w));
    p = __fadd_rn(2.83297682f,      __fmul_rn(p, w));
  }
  return __fmul_rn(p, x);
}

// jax.random.normal element idx of an n-element f32 array under key (k0,k1)
__device__ __forceinline__ float jax_normal_elem(uint32_t k0, uint32_t k1,
                                                 uint32_t idx, uint32_t n) {
  uint32_t b0, b1, bits;
#if JAX_PARTITIONABLE
  (void)n;
  tf2x32(k0, k1, 0u, idx, &b0, &b1);
  bits = b0 ^ b1;
#else
  uint32_t half = n >> 1;
  if (idx < half) { tf2x32(k0, k1, idx, idx + half, &b0, &b1); bits = b0; }
  else            { tf2x32(k0, k1, idx - half, idx, &b0, &b1); bits = b1; }
#endif
  float f = __uint_as_float((bits >> 9) | 0x3f800000u);    // [1,2)
  f = __fadd_rn(f, -1.0f);                                 // [0,1)
  const float lo = -0x1.fffffep-1f;                        // nextafter(-1,0)
  // span = hi - lo rounds to exactly 2.0f in fp32
  float u = __fadd_rn(__fmul_rn(f, 2.0f), lo);
  u = fmaxf(u, lo);
  return __fmul_rn(0x1.6a09e6p+0f /*f32 sqrt(2)*/, erfinv_xla(u));
}

// ---------------------------------------------------------------------------
// Setup: noisy weights (lognormal conductance variation), stored k-major.
// ---------------------------------------------------------------------------
__global__ void setup_weights(const float* __restrict__ w1,
                              const float* __restrict__ w2,
                              const float* __restrict__ w3,
                              const float* __restrict__ w4, Keys K) {
  int e = blockIdx.x * blockDim.x + threadIdx.x;
  if (e >= 3328) return;
  int layer, off, ID, OD, li;
  const float* w;
  if (e < 2048)      { layer = 0; off = 0;    ID = 64; OD = 32; li = e;        w = w1; }
  else if (e < 2816) { layer = 1; off = 2048; ID = 32; OD = 24; li = e - 2048; w = w2; }
  else if (e < 3200) { layer = 2; off = 2816; ID = 24; OD = 16; li = e - 2816; w = w3; }
  else               { layer = 3; off = 3200; ID = 16; OD = 8;  li = e - 3200; w = w4; }
  int j = li / ID, kk = li % ID;
  uint32_t kg0 = K.k[4 * layer + 0], kg1 = K.k[4 * layer + 1];   // ks[2*layer]
  float z = jax_normal_elem(kg0, kg1, (uint32_t)li, (uint32_t)(ID * OD));
  float g = expf(__fmul_rn(z, 0.12f));
  g_nw[off + kk * OD + j] = __fmul_rn(w[li], g);
}

// ---------------------------------------------------------------------------
// One dense "hat" layer: (h*0.99) @ noisyW^T + thermal -> quantize -> clip
// Accumulation is FFMA, k ascending, per output j (cuBLAS-like serial-k).
// ---------------------------------------------------------------------------
template <int ID, int OD, bool RELU>
__device__ __forceinline__ void dense_layer(const float* __restrict__ hin,
                                            float* __restrict__ hout,
                                            const float* __restrict__ sw,
                                            uint32_t kt0, uint32_t kt1,
                                            uint32_t row, uint32_t n) {
  float acc[OD];
#pragma unroll
  for (int j = 0; j < OD; j++) acc[j] = 0.0f;
#pragma unroll
  for (int k = 0; k < ID; k++) {
    float xs = __fmul_rn(hin[k], 0.99f);
#pragma unroll
    for (int j = 0; j < OD; j += 4) {
      float4 wv = *(const float4*)&sw[k * OD + j];
      acc[j + 0] = __fmaf_rn(xs, wv.x, acc[j + 0]);
      acc[j + 1] = __fmaf_rn(xs, wv.y, acc[j + 1]);
      acc[j + 2] = __fmaf_rn(xs, wv.z, acc[j + 2]);
      acc[j + 3] = __fmaf_rn(xs, wv.w, acc[j + 3]);
    }
  }
  uint32_t i0 = row * (uint32_t)OD;
#pragma unroll
  for (int j = 0; j < OD; j++) {
    float z = jax_normal_elem(kt0, kt1, i0 + (uint32_t)j, n);
    float o = __fadd_rn(acc[j], __fmul_rn(z, 8e-07f));
    float q = __fmul_rn(rintf(__fmul_rn(o, 128.0f)), 0.0078125f);
    q = fminf(fmaxf(q, -1.0f), 1.0f);
    hout[j] = RELU ? fmaxf(q, 0.0f) : q;
  }
}

__global__ void __launch_bounds__(TB)
actor_kernel(const float* __restrict__ x, float* __restrict__ out,
             int rows, Keys K) {
  __shared__ float s_w[3328];
  __shared__ float s_x[TB * XSTRIDE];
  int tid = threadIdx.x;

  for (int i = tid; i < 3328; i += TB) s_w[i] = g_nw[i];

  const float4* xg = (const float4*)(x + (size_t)blockIdx.x * TB * 64);
#pragma unroll
  for (int t = 0; t < (TB * 64 / 4) / TB; t++) {
    int idx = tid + t * TB;
    int r = idx >> 4, c = idx & 15;
    *(float4*)&s_x[r * XSTRIDE + c * 4] = xg[idx];
  }
  __syncthreads();

  uint32_t row = blockIdx.x * TB + tid;
  uint32_t urows = (uint32_t)rows;
  const float* xr = &s_x[tid * XSTRIDE];

  float h1[32], h2[24], h3[16], h4[8];
  dense_layer<64, 32, true >(xr, h1, s_w,        K.k[2],  K.k[3],  row, urows * 32u);
  dense_layer<32, 24, true >(h1, h2, s_w + 2048, K.k[6],  K.k[7],  row, urows * 24u);
  dense_layer<24, 16, true >(h2, h3, s_w + 2816, K.k[10], K.k[11], row, urows * 16u);
  dense_layer<16,  8, false>(h3, h4, s_w + 3200, K.k[14], K.k[15], row, urows * 8u);

  float4 o0 = make_float4(tanhf(h4[0]), tanhf(h4[1]), tanhf(h4[2]), tanhf(h4[3]));
  float4 o1 = make_float4(tanhf(h4[4]), tanhf(h4[5]), tanhf(h4[6]), tanhf(h4[7]));
  float* op = out + (size_t)row * 8;
  *(float4*)op       = o0;
  *(float4*)(op + 4) = o1;
}

// ---------------------------------------------------------------------------
extern "C" void kernel_launch(void* const* d_in, const int* in_sizes, int n_in,
                              void* d_out, int out_size) {
  const float* x  = (const float*)d_in[0];
  const float* w1 = (const float*)d_in[1];
  const float* w2 = (const float*)d_in[2];
  const float* w3 = (const float*)d_in[3];
  const float* w4 = (const float*)d_in[4];
  int rows = in_sizes[0] / 64;

  Keys K;
#if JAX_PARTITIONABLE
  for (int i = 0; i < 8; i++) {
    uint32_t a, b;
    tf2x32(0u, 42u, 0u, (uint32_t)i, &a, &b);
    K.k[2 * i] = a; K.k[2 * i + 1] = b;
  }
#else
  uint32_t r0[8], r1[8], res[16];
  for (int i = 0; i < 8; i++) tf2x32(0u, 42u, (uint32_t)i, (uint32_t)(8 + i), &r0[i], &r1[i]);
  for (int i = 0; i < 8; i++) { res[i] = r0[i]; res[8 + i] = r1[i]; }
  for (int i = 0; i < 8; i++) { K.k[2 * i] = res[2 * i]; K.k[2 * i + 1] = res[2 * i + 1]; }
#endif

  setup_weights<<<(3328 + 255) / 256, 256>>>(w1, w2, w3, w4, K);
  actor_kernel<<<rows / TB, TB>>>(x, (float*)d_out, rows, K);
}

// round 2
// speedup vs baseline: 1.4929x; 1.4929x over previous
#include <cuda_runtime.h>
#include <stdint.h>

// ---------------------------------------------------------------------------
// JAX threefry2x32 (partitionable mode, verified in R1):
//   split(key,8): ks[i] = threefry(key,(0,i)); normal elem i uses fold
//   lane0^lane1 of threefry(key,(0,i)).
// ---------------------------------------------------------------------------
#define TB 128

struct Keys { unsigned int k[16]; };   // ks[i] = (k[2i], k[2i+1])

__device__ float g_nw[3328];           // noisy weights, k-major per layer
__device__ float g_tanh[257];          // tanh LUT on the 1/128 grid

__host__ __device__ __forceinline__ void tf2x32(uint32_t k0, uint32_t k1,
                                                uint32_t x0, uint32_t x1,
                                                uint32_t* o0, uint32_t* o1) {
  uint32_t ks2 = k0 ^ k1 ^ 0x1BD11BDAu;
#define TFR(a,b,r) { a += b; b = ((b << (r)) | (b >> (32 - (r)))); b ^= a; }
  x0 += k0; x1 += k1;
  TFR(x0,x1,13) TFR(x0,x1,15) TFR(x0,x1,26) TFR(x0,x1,6)
  x0 += k1;  x1 += ks2 + 1u;
  TFR(x0,x1,17) TFR(x0,x1,29) TFR(x0,x1,16) TFR(x0,x1,24)
  x0 += ks2; x1 += k0 + 2u;
  TFR(x0,x1,13) TFR(x0,x1,15) TFR(x0,x1,26) TFR(x0,x1,6)
  x0 += k0;  x1 += k1 + 3u;
  TFR(x0,x1,17) TFR(x0,x1,29) TFR(x0,x1,16) TFR(x0,x1,24)
  x0 += k1;  x1 += ks2 + 4u;
  TFR(x0,x1,13) TFR(x0,x1,15) TFR(x0,x1,26) TFR(x0,x1,6)
  x0 += ks2; x1 += k0 + 5u;
#undef TFR
  *o0 = x0; *o1 = x1;
}

// --- exact path (weight noise only; ulps here shift every row) -------------
__device__ __forceinline__ float erfinv_xla(float x) {
  float xx = __fmul_rn(x, x);
  float w  = -log1pf(-xx);
  float p;
  if (w < 5.0f) {
    w = __fadd_rn(w, -2.5f);
    p = 2.81022636e-08f;
    p = __fadd_rn(3.43273939e-07f,  __fmul_rn(p, w));
    p = __fadd_rn(-3.5233877e-06f,  __fmul_rn(p, w));
    p = __fadd_rn(-4.39150654e-06f, __fmul_rn(p, w));
    p = __fadd_rn(0.00021858087f,   __fmul_rn(p, w));
    p = __fadd_rn(-0.00125372503f,  __fmul_rn(p, w));
    p = __fadd_rn(-0.00417768164f,  __fmul_rn(p, w));
    p = __fadd_rn(0.246640727f,     __fmul_rn(p, w));
    p = __fadd_rn(1.50140941f,      __fmul_rn(p, w));
  } else {
    w = __fadd_rn(sqrtf(w), -3.0f);
    p = -0.000200214257f;
    p = __fadd_rn(0.000100950558f,  __fmul_rn(p, w));
    p = __fadd_rn(0.00134934322f,   __fmul_rn(p, w));
    p = __fadd_rn(-0.00367342844f,  __fmul_rn(p, w));
    p = __fadd_rn(0.00573950773f,   __fmul_rn(p, w));
    p = __fadd_rn(-0.0076224613f,   __fmul_rn(p, w));
    p = __fadd_rn(0.00943887047f,   __fmul_rn(p, w));
    p = __fadd_rn(1.00167406f,      __fmul_rn(p, w));
    p = __fadd_rn(2.83297682f,      __fmul_rn(p, w));
  }
  return __fmul_rn(p, x);
}

__device__ __forceinline__ float jax_normal_exact(uint32_t k0, uint32_t k1,
                                                  uint32_t idx) {
  uint32_t b0, b1;
  tf2x32(k0, k1, 0u, idx, &b0, &b1);
  uint32_t bits = b0 ^ b1;
  float f = __uint_as_float((bits >> 9) | 0x3f800000u);
  f = __fadd_rn(f, -1.0f);
  const float lo = -0x1.fffffep-1f;
  float u = __fadd_rn(__fmul_rn(f, 2.0f), lo);
  u = fmaxf(u, lo);
  return __fmul_rn(0x1.6a09e6p+0f, erfinv_xla(u));
}

// --- fast thermal path: exact bits, ~1e-3-accurate erfinv, sigma*sqrt2 -----
// folded into the polynomial. Error delta in z flips a quantization decision
// with prob ~2e-4*delta per element -> < 1e-5 added rel_err.
#define SC(a) ((float)((a) * 1.1313708498984761e-06))  // * sqrt(2)*8e-7

__device__ __forceinline__ float add_thermal(uint32_t k0, uint32_t k1,
                                             uint32_t idx, float acc) {
  uint32_t b0, b1;
  tf2x32(k0, k1, 0u, idx, &b0, &b1);
  uint32_t bits = b0 ^ b1;
  float f = __uint_as_float((bits >> 9) | 0x3f800000u) - 1.0f;  // [0,1)
  float u = fmaf(f, 2.0f, -0x1.fffffep-1f);                      // (-1,1)
  float t = fmaf(u, -u, 1.0f);                                   // >= ~1.2e-7
  float w = fminf(-__logf(t), 5.0f);
  w = w - 2.5f;
  float p = SC(2.81022636e-08);
  p = fmaf(p, w, SC(3.43273939e-07));
  p = fmaf(p, w, SC(-3.5233877e-06));
  p = fmaf(p, w, SC(-4.39150654e-06));
  p = fmaf(p, w, SC(0.00021858087));
  p = fmaf(p, w, SC(-0.00125372503));
  p = fmaf(p, w, SC(-0.00417768164));
  p = fmaf(p, w, SC(0.246640727));
  p = fmaf(p, w, SC(1.50140941));
  return fmaf(p, u, acc);
}

// --- packed f32x2 helpers (sm_10x) ------------------------------------------
__device__ __forceinline__ unsigned long long pack2(float a, float b) {
  unsigned long long r;
  asm("mov.b64 %0, {%1, %2};" : "=l"(r) : "f"(a), "f"(b));
  return r;
}
__device__ __forceinline__ void unpack2(unsigned long long v, float& a, float& b) {
  asm("mov.b64 {%0, %1}, %2;" : "=f"(a), "=f"(b) : "l"(v));
}
__device__ __forceinline__ void fma2(unsigned long long& d,
                                     unsigned long long a, unsigned long long b) {
  asm("fma.rn.f32x2 %0, %1, %2, %0;" : "+l"(d) : "l"(a), "l"(b));
}
__device__ __forceinline__ unsigned long long mul2(unsigned long long a,
                                                   unsigned long long b) {
  unsigned long long r;
  asm("mul.rn.f32x2 %0, %1, %2;" : "=l"(r) : "l"(a), "l"(b));
  return r;
}
#define C99P 0x3F7D70A43F7D70A4ull  // (0.99f, 0.99f)

// ---------------------------------------------------------------------------
__global__ void setup_weights(const float* __restrict__ w1,
                              const float* __restrict__ w2,
                              const float* __restrict__ w3,
                              const float* __restrict__ w4, Keys K) {
  int e = blockIdx.x * blockDim.x + threadIdx.x;
  if (e >= 3328) {
    int te = e - 3328;
    if (te < 257) g_tanh[te] = tanhf((te - 128) * 0.0078125f);
    return;
  }
  int layer, off, ID, OD, li;
  const float* w;
  if (e < 2048)      { layer = 0; off = 0;    ID = 64; OD = 32; li = e;        w = w1; }
  else if (e < 2816) { layer = 1; off = 2048; ID = 32; OD = 24; li = e - 2048; w = w2; }
  else if (e < 3200) { layer = 2; off = 2816; ID = 24; OD = 16; li = e - 2816; w = w3; }
  else               { layer = 3; off = 3200; ID = 16; OD = 8;  li = e - 3200; w = w4; }
  int j = li / ID, kk = li % ID;
  float z = jax_normal_exact(K.k[4 * layer + 0], K.k[4 * layer + 1], (uint32_t)li);
  float g = expf(__fmul_rn(z, 0.12f));
  g_nw[off + kk * OD + j] = __fmul_rn(w[li], g);
}

// ---------------------------------------------------------------------------
template <int ID, int OD>
__device__ __forceinline__ void dense_hidden(const float* __restrict__ hin,
                                             float* __restrict__ hout,
                                             const float* __restrict__ sw,
                                             uint32_t kt0, uint32_t kt1,
                                             uint32_t base) {
  unsigned long long acc[OD / 2];
#pragma unroll
  for (int j = 0; j < OD / 2; j++) acc[j] = 0ull;
#pragma unroll
  for (int k = 0; k < ID; k++) {
    unsigned long long xp = mul2(pack2(hin[k], hin[k]), C99P);
    const ulonglong2* wp = (const ulonglong2*)(sw + k * OD);
#pragma unroll
    for (int j = 0; j < OD / 4; j++) {
      ulonglong2 wv = wp[j];
      fma2(acc[2 * j],     xp, wv.x);
      fma2(acc[2 * j + 1], xp, wv.y);
    }
  }
#pragma unroll
  for (int j = 0; j < OD / 2; j++) {
    float a, b;
    unpack2(acc[j], a, b);
    float o0 = add_thermal(kt0, kt1, base + 2 * j,     a);
    float o1 = add_thermal(kt0, kt1, base + 2 * j + 1, b);
    float q0 = __fmul_rn(rintf(__fmul_rn(o0, 128.0f)), 0.0078125f);
    float q1 = __fmul_rn(rintf(__fmul_rn(o1, 128.0f)), 0.0078125f);
    hout[2 * j]     = fminf(fmaxf(q0, 0.0f), 1.0f);   // clip(-1,1)+relu
    hout[2 * j + 1] = fminf(fmaxf(q1, 0.0f), 1.0f);
  }
}

__global__ void __launch_bounds__(TB, 6)
actor_kernel(const float* __restrict__ x, float* __restrict__ out,
             Keys K) {
  __shared__ float s_w[3328];
  __shared__ float s_tanh[257];
  int tid = threadIdx.x;

  {
    const float4* src = (const float4*)g_nw;
    float4* dst = (float4*)s_w;
#pragma unroll
    for (int i = 0; i < 7; i++) {
      int idx = tid + i * TB;
      if (idx < 832) dst[idx] = src[idx];
    }
    for (int i = tid; i < 257; i += TB) s_tanh[i] = g_tanh[i];
  }
  __syncthreads();

  uint32_t row = blockIdx.x * TB + tid;

  // ---- layer 1: x from global (L1-resident), packed accumulate ----
  float h1[32];
  {
    unsigned long long acc[16];
#pragma unroll
    for (int j = 0; j < 16; j++) acc[j] = 0ull;
    const float4* xr = (const float4*)(x + (size_t)row * 64);
#pragma unroll
    for (int k4 = 0; k4 < 16; k4++) {
      float4 xv = __ldg(xr + k4);
      float xk[4] = {xv.x, xv.y, xv.z, xv.w};
#pragma unroll
      for (int c = 0; c < 4; c++) {
        int k = 4 * k4 + c;
        unsigned long long xp = mul2(pack2(xk[c], xk[c]), C99P);
        const ulonglong2* wp = (const ulonglong2*)(s_w + k * 32);
#pragma unroll
        for (int j = 0; j < 8; j++) {
          ulonglong2 wv = wp[j];
          fma2(acc[2 * j],     xp, wv.x);
          fma2(acc[2 * j + 1], xp, wv.y);
        }
      }
    }
    uint32_t base = row * 32u;
#pragma unroll
    for (int j = 0; j < 16; j++) {
      float a, b;
      unpack2(acc[j], a, b);
      float o0 = add_thermal(K.k[2], K.k[3], base + 2 * j,     a);
      float o1 = add_thermal(K.k[2], K.k[3], base + 2 * j + 1, b);
      float q0 = __fmul_rn(rintf(__fmul_rn(o0, 128.0f)), 0.0078125f);
      float q1 = __fmul_rn(rintf(__fmul_rn(o1, 128.0f)), 0.0078125f);
      h1[2 * j]     = fminf(fmaxf(q0, 0.0f), 1.0f);
      h1[2 * j + 1] = fminf(fmaxf(q1, 0.0f), 1.0f);
    }
  }

  float h2[24], h3[16];
  dense_hidden<32, 24>(h1, h2, s_w + 2048, K.k[6],  K.k[7],  row * 24u);
  dense_hidden<24, 16>(h2, h3, s_w + 2816, K.k[10], K.k[11], row * 16u);

  // ---- layer 4: no relu, clip(-1,1), tanh via LUT (grid has 257 values) ----
  float o4[8];
  {
    unsigned long long acc[4];
#pragma unroll
    for (int j = 0; j < 4; j++) acc[j] = 0ull;
    const float* sw = s_w + 3200;
#pragma unroll
    for (int k = 0; k < 16; k++) {
      unsigned long long xp = mul2(pack2(h3[k], h3[k]), C99P);
      const ulonglong2* wp = (const ulonglong2*)(sw + k * 8);
#pragma unroll
      for (int j = 0; j < 2; j++) {
        ulonglong2 wv = wp[j];
        fma2(acc[2 * j],     xp, wv.x);
        fma2(acc[2 * j + 1], xp, wv.y);
      }
    }
    uint32_t base = row * 8u;
#pragma unroll
    for (int j = 0; j < 4; j++) {
      float a, b;
      unpack2(acc[j], a, b);
      float o0 = add_thermal(K.k[14], K.k[15], base + 2 * j,     a);
      float o1 = add_thermal(K.k[14], K.k[15], base + 2 * j + 1, b);
      float r0 = fminf(fmaxf(rintf(__fmul_rn(o0, 128.0f)), -128.0f), 128.0f);
      float r1 = fminf(fmaxf(rintf(__fmul_rn(o1, 128.0f)), -128.0f), 128.0f);
      o4[2 * j]     = s_tanh[__float2int_rn(r0) + 128];
      o4[2 * j + 1] = s_tanh[__float2int_rn(r1) + 128];
    }
  }

  float4 v0 = make_float4(o4[0], o4[1], o4[2], o4[3]);
  float4 v1 = make_float4(o4[4], o4[5], o4[6], o4[7]);
  float* op = out + (size_t)row * 8;
  *(float4*)op       = v0;
  *(float4*)(op + 4) = v1;
}

// ---------------------------------------------------------------------------
extern "C" void kernel_launch(void* const* d_in, const int* in_sizes, int n_in,
                              void* d_out, int out_size) {
  const float* x  = (const float*)d_in[0];
  const float* w1 = (const float*)d_in[1];
  const float* w2 = (const float*)d_in[2];
  const float* w3 = (const float*)d_in[3];
  const float* w4 = (const float*)d_in[4];
  int rows = in_sizes[0] / 64;

  Keys K;
  for (int i = 0; i < 8; i++) {
    uint32_t a, b;
    tf2x32(0u, 42u, 0u, (uint32_t)i, &a, &b);
    K.k[2 * i] = a; K.k[2 * i + 1] = b;
  }

  setup_weights<<<(3328 + 257 + 255) / 256, 256>>>(w1, w2, w3, w4, K);
  actor_kernel<<<rows / TB, TB>>>(x, (float*)d_out, K);
}

// round 3
// speedup vs baseline: 2.7775x; 1.8605x over previous
#include <cuda_runtime.h>
#include <stdint.h>

// ---------------------------------------------------------------------------
// JAX threefry2x32 (partitionable mode, verified R1):
//   split(key,8): ks[i] = threefry(key,(0,i)); normal elem i folds
//   lane0^lane1 of threefry(key,(0,i)).
// R3: thermal noise evaluated LAZILY — only when acc*128 is within 1.5e-3 of
// a round-half-even boundary (warp-ballot uniform branch). Rigorous bound on
// |128*fl(acc+z*8e-7) - 128*acc| <= 7.5e-4 < band.
// ---------------------------------------------------------------------------
#define TB 128

struct Keys { unsigned int k[16]; };   // ks[i] = (k[2i], k[2i+1])

__device__ float g_nw[3328];           // noisy weights, k-major per layer
__device__ float g_tanh[257];          // tanh LUT on the 1/128 grid

__host__ __device__ __forceinline__ void tf2x32(uint32_t k0, uint32_t k1,
                                                uint32_t x0, uint32_t x1,
                                                uint32_t* o0, uint32_t* o1) {
  uint32_t ks2 = k0 ^ k1 ^ 0x1BD11BDAu;
#define TFR(a,b,r) { a += b; b = ((b << (r)) | (b >> (32 - (r)))); b ^= a; }
  x0 += k0; x1 += k1;
  TFR(x0,x1,13) TFR(x0,x1,15) TFR(x0,x1,26) TFR(x0,x1,6)
  x0 += k1;  x1 += ks2 + 1u;
  TFR(x0,x1,17) TFR(x0,x1,29) TFR(x0,x1,16) TFR(x0,x1,24)
  x0 += ks2; x1 += k0 + 2u;
  TFR(x0,x1,13) TFR(x0,x1,15) TFR(x0,x1,26) TFR(x0,x1,6)
  x0 += k0;  x1 += k1 + 3u;
  TFR(x0,x1,17) TFR(x0,x1,29) TFR(x0,x1,16) TFR(x0,x1,24)
  x0 += k1;  x1 += ks2 + 4u;
  TFR(x0,x1,13) TFR(x0,x1,15) TFR(x0,x1,26) TFR(x0,x1,6)
  x0 += ks2; x1 += k0 + 5u;
#undef TFR
  *o0 = x0; *o1 = x1;
}

// --- exact path (weight noise; ulps here shift every row) -------------------
__device__ __forceinline__ float erfinv_xla(float x) {
  float xx = __fmul_rn(x, x);
  float w  = -log1pf(-xx);
  float p;
  if (w < 5.0f) {
    w = __fadd_rn(w, -2.5f);
    p = 2.81022636e-08f;
    p = __fadd_rn(3.43273939e-07f,  __fmul_rn(p, w));
    p = __fadd_rn(-3.5233877e-06f,  __fmul_rn(p, w));
    p = __fadd_rn(-4.39150654e-06f, __fmul_rn(p, w));
    p = __fadd_rn(0.00021858087f,   __fmul_rn(p, w));
    p = __fadd_rn(-0.00125372503f,  __fmul_rn(p, w));
    p = __fadd_rn(-0.00417768164f,  __fmul_rn(p, w));
    p = __fadd_rn(0.246640727f,     __fmul_rn(p, w));
    p = __fadd_rn(1.50140941f,      __fmul_rn(p, w));
  } else {
    w = __fadd_rn(sqrtf(w), -3.0f);
    p = -0.000200214257f;
    p = __fadd_rn(0.000100950558f,  __fmul_rn(p, w));
    p = __fadd_rn(0.00134934322f,   __fmul_rn(p, w));
    p = __fadd_rn(-0.00367342844f,  __fmul_rn(p, w));
    p = __fadd_rn(0.00573950773f,   __fmul_rn(p, w));
    p = __fadd_rn(-0.0076224613f,   __fmul_rn(p, w));
    p = __fadd_rn(0.00943887047f,   __fmul_rn(p, w));
    p = __fadd_rn(1.00167406f,      __fmul_rn(p, w));
    p = __fadd_rn(2.83297682f,      __fmul_rn(p, w));
  }
  return __fmul_rn(p, x);
}

__device__ __forceinline__ float jax_normal_exact(uint32_t k0, uint32_t k1,
                                                  uint32_t idx) {
  uint32_t b0, b1;
  tf2x32(k0, k1, 0u, idx, &b0, &b1);
  uint32_t bits = b0 ^ b1;
  float f = __uint_as_float((bits >> 9) | 0x3f800000u);
  f = __fadd_rn(f, -1.0f);
  const float lo = -0x1.fffffep-1f;
  float u = __fadd_rn(__fmul_rn(f, 2.0f), lo);
  u = fmaxf(u, lo);
  return __fmul_rn(0x1.6a09e6p+0f, erfinv_xla(u));
}

// --- fast thermal path (rarely executed now): exact bits, ~1e-3 erfinv ------
#define SC(a) ((float)((a) * 1.1313708498984761e-06))  // * sqrt(2)*8e-7

__device__ __noinline__ float add_thermal(uint32_t k0, uint32_t k1,
                                          uint32_t idx, float acc) {
  uint32_t b0, b1;
  tf2x32(k0, k1, 0u, idx, &b0, &b1);
  uint32_t bits = b0 ^ b1;
  float f = __uint_as_float((bits >> 9) | 0x3f800000u) - 1.0f;  // [0,1)
  float u = fmaf(f, 2.0f, -0x1.fffffep-1f);                      // (-1,1)
  float t = fmaf(u, -u, 1.0f);
  float w = fminf(-__logf(t), 5.0f);
  w = w - 2.5f;
  float p = SC(2.81022636e-08);
  p = fmaf(p, w, SC(3.43273939e-07));
  p = fmaf(p, w, SC(-3.5233877e-06));
  p = fmaf(p, w, SC(-4.39150654e-06));
  p = fmaf(p, w, SC(0.00021858087));
  p = fmaf(p, w, SC(-0.00125372503));
  p = fmaf(p, w, SC(-0.00417768164));
  p = fmaf(p, w, SC(0.246640727));
  p = fmaf(p, w, SC(1.50140941));
  return fmaf(p, u, acc);
}

// Lazy-quantized element: returns rintf(o*128) with o = acc (+ thermal noise
// only when it can matter). Uniform warp-ballot branch.
__device__ __forceinline__ float quant_r(uint32_t kt0, uint32_t kt1,
                                         uint32_t idx, float acc) {
  float y = __fmul_rn(acc, 128.0f);
  float r = rintf(y);
  bool need = fabsf(__fadd_rn(y, -r)) >= 0.4985f;
  if (__builtin_expect((int)__ballot_sync(0xffffffffu, need), 0)) {
    float o = add_thermal(kt0, kt1, idx, acc);
    r = rintf(__fmul_rn(o, 128.0f));
  }
  return r;
}

// --- packed f32x2 helpers (sm_10x) ------------------------------------------
__device__ __forceinline__ unsigned long long pack2(float a, float b) {
  unsigned long long r;
  asm("mov.b64 %0, {%1, %2};" : "=l"(r) : "f"(a), "f"(b));
  return r;
}
__device__ __forceinline__ void unpack2(unsigned long long v, float& a, float& b) {
  asm("mov.b64 {%0, %1}, %2;" : "=f"(a), "=f"(b) : "l"(v));
}
__device__ __forceinline__ void fma2(unsigned long long& d,
                                     unsigned long long a, unsigned long long b) {
  asm("fma.rn.f32x2 %0, %1, %2, %0;" : "+l"(d) : "l"(a), "l"(b));
}
__device__ __forceinline__ unsigned long long mul2(unsigned long long a,
                                                   unsigned long long b) {
  unsigned long long r;
  asm("mul.rn.f32x2 %0, %1, %2;" : "=l"(r) : "l"(a), "l"(b));
  return r;
}
#define C99P 0x3F7D70A43F7D70A4ull  // (0.99f, 0.99f)

// ---------------------------------------------------------------------------
__global__ void setup_weights(const float* __restrict__ w1,
                              const float* __restrict__ w2,
                              const float* __restrict__ w3,
                              const float* __restrict__ w4, Keys K) {
  int e = blockIdx.x * blockDim.x + threadIdx.x;
  if (e >= 3328) {
    int te = e - 3328;
    if (te < 257) g_tanh[te] = tanhf((te - 128) * 0.0078125f);
    return;
  }
  int layer, off, ID, OD, li;
  const float* w;
  if (e < 2048)      { layer = 0; off = 0;    ID = 64; OD = 32; li = e;        w = w1; }
  else if (e < 2816) { layer = 1; off = 2048; ID = 32; OD = 24; li = e - 2048; w = w2; }
  else if (e < 3200) { layer = 2; off = 2816; ID = 24; OD = 16; li = e - 2816; w = w3; }
  else               { layer = 3; off = 3200; ID = 16; OD = 8;  li = e - 3200; w = w4; }
  int j = li / ID, kk = li % ID;
  float z = jax_normal_exact(K.k[4 * layer + 0], K.k[4 * layer + 1], (uint32_t)li);
  float g = expf(__fmul_rn(z, 0.12f));
  g_nw[off + kk * OD + j] = __fmul_rn(w[li], g);
}

// ---------------------------------------------------------------------------
template <int ID, int OD>
__device__ __forceinline__ void dense_hidden(const float* __restrict__ hin,
                                             float* __restrict__ hout,
                                             const float* __restrict__ sw,
                                             uint32_t kt0, uint32_t kt1,
                                             uint32_t base) {
  unsigned long long acc[OD / 2];
#pragma unroll
  for (int j = 0; j < OD / 2; j++) acc[j] = 0ull;
#pragma unroll
  for (int k = 0; k < ID; k++) {
    unsigned long long xp = mul2(pack2(hin[k], hin[k]), C99P);
    const ulonglong2* wp = (const ulonglong2*)(sw + k * OD);
#pragma unroll
    for (int j = 0; j < OD / 4; j++) {
      ulonglong2 wv = wp[j];
      fma2(acc[2 * j],     xp, wv.x);
      fma2(acc[2 * j + 1], xp, wv.y);
    }
  }
#pragma unroll
  for (int j = 0; j < OD / 2; j++) {
    float a, b;
    unpack2(acc[j], a, b);
    float r0 = quant_r(kt0, kt1, base + 2 * j,     a);
    float r1 = quant_r(kt0, kt1, base + 2 * j + 1, b);
    // clip(-1,1) + relu, on the integer grid then scale
    hout[2 * j]     = __fmul_rn(fminf(fmaxf(r0, 0.0f), 128.0f), 0.0078125f);
    hout[2 * j + 1] = __fmul_rn(fminf(fmaxf(r1, 0.0f), 128.0f), 0.0078125f);
  }
}

__global__ void __launch_bounds__(TB, 6)
actor_kernel(const float* __restrict__ x, float* __restrict__ out,
             Keys K) {
  __shared__ float s_w[3328];
  __shared__ float s_tanh[257];
  int tid = threadIdx.x;

  {
    const float4* src = (const float4*)g_nw;
    float4* dst = (float4*)s_w;
#pragma unroll
    for (int i = 0; i < 7; i++) {
      int idx = tid + i * TB;
      if (idx < 832) dst[idx] = src[idx];
    }
    for (int i = tid; i < 257; i += TB) s_tanh[i] = g_tanh[i];
  }
  __syncthreads();

  uint32_t row = blockIdx.x * TB + tid;

  // ---- layer 1: x streamed from global, packed accumulate ----
  float h1[32];
  {
    unsigned long long acc[16];
#pragma unroll
    for (int j = 0; j < 16; j++) acc[j] = 0ull;
    const float4* xr = (const float4*)(x + (size_t)row * 64);
#pragma unroll
    for (int k4 = 0; k4 < 16; k4++) {
      float4 xv = __ldg(xr + k4);
      float xk[4] = {xv.x, xv.y, xv.z, xv.w};
#pragma unroll
      for (int c = 0; c < 4; c++) {
        int k = 4 * k4 + c;
        unsigned long long xp = mul2(pack2(xk[c], xk[c]), C99P);
        const ulonglong2* wp = (const ulonglong2*)(s_w + k * 32);
#pragma unroll
        for (int j = 0; j < 8; j++) {
          ulonglong2 wv = wp[j];
          fma2(acc[2 * j],     xp, wv.x);
          fma2(acc[2 * j + 1], xp, wv.y);
        }
      }
    }
    uint32_t base = row * 32u;
#pragma unroll
    for (int j = 0; j < 16; j++) {
      float a, b;
      unpack2(acc[j], a, b);
      float r0 = quant_r(K.k[2], K.k[3], base + 2 * j,     a);
      float r1 = quant_r(K.k[2], K.k[3], base + 2 * j + 1, b);
      h1[2 * j]     = __fmul_rn(fminf(fmaxf(r0, 0.0f), 128.0f), 0.0078125f);
      h1[2 * j + 1] = __fmul_rn(fminf(fmaxf(r1, 0.0f), 128.0f), 0.0078125f);
    }
  }

  float h2[24], h3[16];
  dense_hidden<32, 24>(h1, h2, s_w + 2048, K.k[6],  K.k[7],  row * 24u);
  dense_hidden<24, 16>(h2, h3, s_w + 2816, K.k[10], K.k[11], row * 16u);

  // ---- layer 4: no relu, clip(-1,1), tanh via 1/128-grid LUT ----
  float o4[8];
  {
    unsigned long long acc[4];
#pragma unroll
    for (int j = 0; j < 4; j++) acc[j] = 0ull;
    const float* sw = s_w + 3200;
#pragma unroll
    for (int k = 0; k < 16; k++) {
      unsigned long long xp = mul2(pack2(h3[k], h3[k]), C99P);
      const ulonglong2* wp = (const ulonglong2*)(sw + k * 8);
#pragma unroll
      for (int j = 0; j < 2; j++) {
        ulonglong2 wv = wp[j];
        fma2(acc[2 * j],     xp, wv.x);
        fma2(acc[2 * j + 1], xp, wv.y);
      }
    }
    uint32_t base = row * 8u;
#pragma unroll
    for (int j = 0; j < 4; j++) {
      float a, b;
      unpack2(acc[j], a, b);
      float r0 = quant_r(K.k[14], K.k[15], base + 2 * j,     a);
      float r1 = quant_r(K.k[14], K.k[15], base + 2 * j + 1, b);
      r0 = fminf(fmaxf(r0, -128.0f), 128.0f);
      r1 = fminf(fmaxf(r1, -128.0f), 128.0f);
      o4[2 * j]     = s_tanh[__float2int_rn(r0) + 128];
      o4[2 * j + 1] = s_tanh[__float2int_rn(r1) + 128];
    }
  }

  float4 v0 = make_float4(o4[0], o4[1], o4[2], o4[3]);
  float4 v1 = make_float4(o4[4], o4[5], o4[6], o4[7]);
  float* op = out + (size_t)row * 8;
  *(float4*)op       = v0;
  *(float4*)(op + 4) = v1;
}

// ---------------------------------------------------------------------------
extern "C" void kernel_launch(void* const* d_in, const int* in_sizes, int n_in,
                              void* d_out, int out_size) {
  const float* x  = (const float*)d_in[0];
  const float* w1 = (const float*)d_in[1];
  const float* w2 = (const float*)d_in[2];
  const float* w3 = (const float*)d_in[3];
  const float* w4 = (const float*)d_in[4];
  int rows = in_sizes[0] / 64;

  Keys K;
  for (int i = 0; i < 8; i++) {
    uint32_t a, b;
    tf2x32(0u, 42u, 0u, (uint32_t)i, &a, &b);
    K.k[2 * i] = a; K.k[2 * i + 1] = b;
  }

  setup_weights<<<(3328 + 257 + 255) / 256, 256>>>(w1, w2, w3, w4, K);
  actor_kernel<<<rows / TB, TB>>>(x, (float*)d_out, K);
}